// round 1
// baseline (speedup 1.0000x reference)
#include <cuda_runtime.h>

// Problem constants
#define B_    32
#define CIN   128
#define H_    56
#define HW    3136          // 56*56
#define COUT  256
#define KTOT  1152          // CIN*9
#define E_    4
#define R_    16
#define KERN_PER_B (COUT*KTOT)   // 294912
#define CONV4_PER_E (KERN_PER_B/4) // 73728

// Scratch (static device allocations are allowed; cudaMalloc is not)
__device__ float g_gap[B_ * CIN];
__device__ float g_routing[B_ * E_];
__device__ float g_kern[(size_t)B_ * KERN_PER_B];   // 37.7 MB mixed kernels

// ---------------------------------------------------------------------------
// packed f32x2 helpers (Blackwell FFMA2 path — 2x fp32 FMA throughput)
// ---------------------------------------------------------------------------
__device__ __forceinline__ unsigned long long ffma2(unsigned long long a,
                                                    unsigned long long b,
                                                    unsigned long long c) {
    unsigned long long d;
    asm("fma.rn.f32x2 %0, %1, %2, %3;" : "=l"(d) : "l"(a), "l"(b), "l"(c));
    return d;
}
__device__ __forceinline__ unsigned long long pack2(float lo, float hi) {
    unsigned long long r;
    asm("mov.b64 %0, {%1, %2};" : "=l"(r) : "f"(lo), "f"(hi));
    return r;
}
__device__ __forceinline__ void unpack2(unsigned long long v, float& lo, float& hi) {
    asm("mov.b64 {%0, %1}, %2;" : "=f"(lo), "=f"(hi) : "l"(v));
}

// ---------------------------------------------------------------------------
// 1) Global average pool: one block per (b, c), reduce 3136 elements
// ---------------------------------------------------------------------------
__global__ void gap_kernel(const float* __restrict__ x) {
    const int idx = blockIdx.x;                   // b*CIN + c
    const float* p = x + (size_t)idx * HW;
    float s = 0.f;
    for (int i = threadIdx.x; i < HW; i += 256) s += p[i];
    #pragma unroll
    for (int o = 16; o > 0; o >>= 1) s += __shfl_xor_sync(0xffffffffu, s, o);
    __shared__ float sm[8];
    if ((threadIdx.x & 31) == 0) sm[threadIdx.x >> 5] = s;
    __syncthreads();
    if (threadIdx.x < 8) {
        s = sm[threadIdx.x];
        s += __shfl_xor_sync(0xffu, s, 4);
        s += __shfl_xor_sync(0xffu, s, 2);
        s += __shfl_xor_sync(0xffu, s, 1);
        if (threadIdx.x == 0) g_gap[idx] = s * (1.0f / 3136.0f);
    }
}

// ---------------------------------------------------------------------------
// 2) Router MLP + softmax(logits/30): one thread per sample
// ---------------------------------------------------------------------------
__global__ void routing_kernel(const float* __restrict__ w1, const float* __restrict__ b1,
                               const float* __restrict__ w2, const float* __restrict__ b2) {
    const int b = threadIdx.x;
    if (b >= B_) return;
    float h[R_];
    #pragma unroll
    for (int r = 0; r < R_; r++) {
        float s = b1[r];
        for (int c = 0; c < CIN; c++) s += g_gap[b * CIN + c] * w1[r * CIN + c];
        h[r] = fmaxf(s, 0.f);
    }
    float lg[E_];
    float mx = -1e30f;
    #pragma unroll
    for (int e = 0; e < E_; e++) {
        float s = b2[e];
        #pragma unroll
        for (int r = 0; r < R_; r++) s += h[r] * w2[e * R_ + r];
        lg[e] = s * (1.0f / 30.0f);
        mx = fmaxf(mx, lg[e]);
    }
    float den = 0.f;
    #pragma unroll
    for (int e = 0; e < E_; e++) { lg[e] = __expf(lg[e] - mx); den += lg[e]; }
    const float inv = 1.0f / den;
    #pragma unroll
    for (int e = 0; e < E_; e++) g_routing[b * E_ + e] = lg[e] * inv;
}

// ---------------------------------------------------------------------------
// 3) Mix expert kernels per sample: kern[b] = sum_e r[b,e] * convs[e]
// ---------------------------------------------------------------------------
__global__ void mix_kernel(const float* __restrict__ convs) {
    const int b = blockIdx.y;
    const int j = blockIdx.x * 256 + threadIdx.x;      // < CONV4_PER_E
    const float r0 = g_routing[b * 4 + 0];
    const float r1 = g_routing[b * 4 + 1];
    const float r2 = g_routing[b * 4 + 2];
    const float r3 = g_routing[b * 4 + 3];
    const float4* c = (const float4*)convs;
    float4 v0 = c[0 * CONV4_PER_E + j];
    float4 v1 = c[1 * CONV4_PER_E + j];
    float4 v2 = c[2 * CONV4_PER_E + j];
    float4 v3 = c[3 * CONV4_PER_E + j];
    float4 o;
    o.x = r0 * v0.x + r1 * v1.x + r2 * v2.x + r3 * v3.x;
    o.y = r0 * v0.y + r1 * v1.y + r2 * v2.y + r3 * v3.y;
    o.z = r0 * v0.z + r1 * v1.z + r2 * v2.z + r3 * v3.z;
    o.w = r0 * v0.w + r1 * v1.w + r2 * v2.w + r3 * v3.w;
    ((float4*)g_kern)[(size_t)b * CONV4_PER_E + j] = o;
}

// ---------------------------------------------------------------------------
// 4) Per-sample 3x3 conv as implicit GEMM.
//    C[M=256, N=3136] = A[M, K=1152] * B[K, N] (B = im2col of x[b])
//    Block tile 128x128, BK=16, thread tile 8x8 (accumulators paired along M
//    so A-pairs come straight from LDS.64; FFMA2 packed math).
// ---------------------------------------------------------------------------
__global__ void __launch_bounds__(256, 2)
conv_kernel(const float* __restrict__ x, float* __restrict__ out) {
    __shared__ __align__(16) float As[16][128];   // [k][m]
    __shared__ __align__(16) float Bs[16][128];   // [k][n]

    const int b  = blockIdx.z;
    const int m0 = blockIdx.y * 128;
    const int n0 = blockIdx.x * 128;
    const int tid = threadIdx.x;
    const int tx = tid & 15;          // n direction (8 cols each)
    const int ty = tid >> 4;          // m direction (8 rows each)

    const float* kb = g_kern + (size_t)b * KERN_PER_B;
    const float* xb = x + (size_t)b * CIN * HW;

    unsigned long long acc[4][8];     // acc[i][j] = rows (2i, 2i+1), col j
    #pragma unroll
    for (int i = 0; i < 4; i++)
        #pragma unroll
        for (int j = 0; j < 8; j++) acc[i][j] = 0ull;

    for (int k0 = 0; k0 < KTOT; k0 += 16) {
        // --- load A tile (transpose to k-major) ---
        #pragma unroll
        for (int q = 0; q < 2; q++) {
            int idx = q * 256 + tid;
            int row = idx >> 2;
            int kq  = (idx & 3) * 4;
            float4 v = *(const float4*)(kb + (size_t)(m0 + row) * KTOT + k0 + kq);
            As[kq + 0][row] = v.x;
            As[kq + 1][row] = v.y;
            As[kq + 2][row] = v.z;
            As[kq + 3][row] = v.w;
        }
        // --- load B tile (im2col on the fly) ---
        #pragma unroll
        for (int q = 0; q < 8; q++) {
            int idx = q * 256 + tid;
            int kk  = idx >> 7;
            int nl  = idx & 127;
            int k   = k0 + kk;
            int ci  = k / 9;
            int rem = k - ci * 9;
            int kh  = rem / 3;
            int kw  = rem - kh * 3;
            int n   = n0 + nl;
            float v = 0.f;
            if (n < HW) {
                int oh = n / H_;
                int ow = n - oh * H_;
                int ih = oh + kh - 1;
                int iw = ow + kw - 1;
                if (ih >= 0 && ih < H_ && iw >= 0 && iw < H_)
                    v = xb[ci * HW + ih * H_ + iw];
            }
            Bs[kk][nl] = v;
        }
        __syncthreads();

        #pragma unroll
        for (int kk = 0; kk < 16; kk++) {
            const unsigned long long* Ap =
                (const unsigned long long*)&As[kk][ty * 8];
            unsigned long long ap0 = Ap[0], ap1 = Ap[1], ap2 = Ap[2], ap3 = Ap[3];
            float4 bq0 = *(const float4*)&Bs[kk][tx * 8];
            float4 bq1 = *(const float4*)&Bs[kk][tx * 8 + 4];
            float bv[8] = {bq0.x, bq0.y, bq0.z, bq0.w, bq1.x, bq1.y, bq1.z, bq1.w};
            #pragma unroll
            for (int j = 0; j < 8; j++) {
                unsigned long long bp = pack2(bv[j], bv[j]);
                acc[0][j] = ffma2(ap0, bp, acc[0][j]);
                acc[1][j] = ffma2(ap1, bp, acc[1][j]);
                acc[2][j] = ffma2(ap2, bp, acc[2][j]);
                acc[3][j] = ffma2(ap3, bp, acc[3][j]);
            }
        }
        __syncthreads();
    }

    // --- epilogue: unpack and store (8 cols per thread are all-valid or all-invalid
    //     because HW-3072=64 is a multiple of 8 and aligns to tx*8 boundaries) ---
    if (n0 + tx * 8 < HW) {
        #pragma unroll
        for (int i = 0; i < 4; i++) {
            float lo[8], hi[8];
            #pragma unroll
            for (int j = 0; j < 8; j++) unpack2(acc[i][j], lo[j], hi[j]);
            int m = m0 + ty * 8 + 2 * i;
            float* o0 = out + ((size_t)(b * COUT + m) * HW) + n0 + tx * 8;
            float* o1 = o0 + HW;
            *(float4*)(o0)     = make_float4(lo[0], lo[1], lo[2], lo[3]);
            *(float4*)(o0 + 4) = make_float4(lo[4], lo[5], lo[6], lo[7]);
            *(float4*)(o1)     = make_float4(hi[0], hi[1], hi[2], hi[3]);
            *(float4*)(o1 + 4) = make_float4(hi[4], hi[5], hi[6], hi[7]);
        }
    }
}

// ---------------------------------------------------------------------------
extern "C" void kernel_launch(void* const* d_in, const int* in_sizes, int n_in,
                              void* d_out, int out_size) {
    const float* x     = (const float*)d_in[0];
    const float* convs = (const float*)d_in[1];
    const float* w1    = (const float*)d_in[2];
    const float* b1    = (const float*)d_in[3];
    const float* w2    = (const float*)d_in[4];
    const float* b2    = (const float*)d_in[5];
    float* out = (float*)d_out;

    gap_kernel<<<B_ * CIN, 256>>>(x);
    routing_kernel<<<1, 32>>>(w1, b1, w2, b2);
    mix_kernel<<<dim3(CONV4_PER_E / 256, B_), 256>>>(convs);
    conv_kernel<<<dim3((HW + 127) / 128, COUT / 128, B_), 256>>>(x, out);
}

// round 3
// speedup vs baseline: 1.7455x; 1.7455x over previous
#include <cuda_runtime.h>
#include <cuda_bf16.h>
#include <cstdint>

// Problem constants
#define B_    32
#define CIN   128
#define H_    56
#define HW    3136          // 56*56
#define COUT  256
#define KTOT  1152          // CIN*9
#define E_    4
#define R_    16
#define KERN_PER_B (COUT*KTOT)      // 294912
#define CONV4_PER_E (KERN_PER_B/4)  // 73728

// Scratch
__device__ float g_gap[B_ * CIN];
__device__ float g_routing[B_ * E_];
// mixed kernels, bf16 split: hi + lo, packed 2 bf16 per uint (element order)
__device__ unsigned int g_kh[(size_t)B_ * KERN_PER_B / 2];
__device__ unsigned int g_kl[(size_t)B_ * KERN_PER_B / 2];

// ---------------------------------------------------------------------------
// helpers
// ---------------------------------------------------------------------------
__device__ __forceinline__ uint32_t smem_u32(const void* p) {
    uint32_t a;
    asm("{ .reg .u64 t; cvta.to.shared.u64 t, %1; cvt.u32.u64 %0, t; }"
        : "=r"(a) : "l"(p));
    return a;
}
__device__ __forceinline__ void ldmx4(uint32_t* r, uint32_t addr) {
    asm volatile("ldmatrix.sync.aligned.m8n8.x4.shared.b16 {%0,%1,%2,%3}, [%4];"
                 : "=r"(r[0]), "=r"(r[1]), "=r"(r[2]), "=r"(r[3]) : "r"(addr));
}
__device__ __forceinline__ void mma_bf16(float* d, const uint32_t* a, const uint32_t* b) {
    asm volatile(
        "mma.sync.aligned.m16n8k16.row.col.f32.bf16.bf16.f32 "
        "{%0,%1,%2,%3},{%4,%5,%6,%7},{%8,%9},{%0,%1,%2,%3};"
        : "+f"(d[0]), "+f"(d[1]), "+f"(d[2]), "+f"(d[3])
        : "r"(a[0]), "r"(a[1]), "r"(a[2]), "r"(a[3]), "r"(b[0]), "r"(b[1]));
}
__device__ __forceinline__ void split_hl(float v, __nv_bfloat16& h, __nv_bfloat16& l) {
    h = __float2bfloat16_rn(v);
    l = __float2bfloat16_rn(v - __bfloat162float(h));
}
__device__ __forceinline__ uint32_t pack_bf2(__nv_bfloat16 a, __nv_bfloat16 b) {
    __nv_bfloat162 t = __halves2bfloat162(a, b);
    return *reinterpret_cast<uint32_t*>(&t);
}

// ---------------------------------------------------------------------------
// 1) Global average pool
// ---------------------------------------------------------------------------
__global__ void gap_kernel(const float* __restrict__ x) {
    const int idx = blockIdx.x;
    const float* p = x + (size_t)idx * HW;
    float s = 0.f;
    for (int i = threadIdx.x; i < HW; i += 256) s += p[i];
    #pragma unroll
    for (int o = 16; o > 0; o >>= 1) s += __shfl_xor_sync(0xffffffffu, s, o);
    __shared__ float sm[8];
    if ((threadIdx.x & 31) == 0) sm[threadIdx.x >> 5] = s;
    __syncthreads();
    if (threadIdx.x < 8) {
        s = sm[threadIdx.x];
        s += __shfl_xor_sync(0xffu, s, 4);
        s += __shfl_xor_sync(0xffu, s, 2);
        s += __shfl_xor_sync(0xffu, s, 1);
        if (threadIdx.x == 0) g_gap[idx] = s * (1.0f / 3136.0f);
    }
}

// ---------------------------------------------------------------------------
// 2) Router MLP + softmax(logits/30)
// ---------------------------------------------------------------------------
__global__ void routing_kernel(const float* __restrict__ w1, const float* __restrict__ b1,
                               const float* __restrict__ w2, const float* __restrict__ b2) {
    const int b = threadIdx.x;
    if (b >= B_) return;
    float h[R_];
    #pragma unroll
    for (int r = 0; r < R_; r++) {
        float s = b1[r];
        for (int c = 0; c < CIN; c++) s += g_gap[b * CIN + c] * w1[r * CIN + c];
        h[r] = fmaxf(s, 0.f);
    }
    float lg[E_];
    float mx = -1e30f;
    #pragma unroll
    for (int e = 0; e < E_; e++) {
        float s = b2[e];
        #pragma unroll
        for (int r = 0; r < R_; r++) s += h[r] * w2[e * R_ + r];
        lg[e] = s * (1.0f / 30.0f);
        mx = fmaxf(mx, lg[e]);
    }
    float den = 0.f;
    #pragma unroll
    for (int e = 0; e < E_; e++) { lg[e] = __expf(lg[e] - mx); den += lg[e]; }
    const float inv = 1.0f / den;
    #pragma unroll
    for (int e = 0; e < E_; e++) g_routing[b * E_ + e] = lg[e] * inv;
}

// ---------------------------------------------------------------------------
// 3) Mix expert kernels + bf16 hi/lo split
// ---------------------------------------------------------------------------
__global__ void mix_kernel(const float* __restrict__ convs) {
    const int b = blockIdx.y;
    const int j = blockIdx.x * 256 + threadIdx.x;      // float4 index < CONV4_PER_E
    const float r0 = g_routing[b * 4 + 0];
    const float r1 = g_routing[b * 4 + 1];
    const float r2 = g_routing[b * 4 + 2];
    const float r3 = g_routing[b * 4 + 3];
    const float4* c = (const float4*)convs;
    float4 v0 = c[0 * CONV4_PER_E + j];
    float4 v1 = c[1 * CONV4_PER_E + j];
    float4 v2 = c[2 * CONV4_PER_E + j];
    float4 v3 = c[3 * CONV4_PER_E + j];
    float o[4];
    o[0] = r0 * v0.x + r1 * v1.x + r2 * v2.x + r3 * v3.x;
    o[1] = r0 * v0.y + r1 * v1.y + r2 * v2.y + r3 * v3.y;
    o[2] = r0 * v0.z + r1 * v1.z + r2 * v2.z + r3 * v3.z;
    o[3] = r0 * v0.w + r1 * v1.w + r2 * v2.w + r3 * v3.w;
    __nv_bfloat16 h[4], l[4];
    #pragma unroll
    for (int i = 0; i < 4; i++) split_hl(o[i], h[i], l[i]);
    uint2 hp = make_uint2(pack_bf2(h[0], h[1]), pack_bf2(h[2], h[3]));
    uint2 lp = make_uint2(pack_bf2(l[0], l[1]), pack_bf2(l[2], l[3]));
    ((uint2*)g_kh)[(size_t)b * (KERN_PER_B / 4) + j] = hp;
    ((uint2*)g_kl)[(size_t)b * (KERN_PER_B / 4) + j] = lp;
}

// ---------------------------------------------------------------------------
// 4) Per-sample implicit GEMM on mma.sync (bf16 3-pass split, fp32 accumulate)
//    CTA tile 128m x 128n, BK=32 (36 stages). 8 warps: warp tile 64m x 32n.
//    SMEM rows padded to 80B for conflict-free ldmatrix.
// ---------------------------------------------------------------------------
#define BK    32
#define RS    80                 // bytes per smem row (32 bf16 = 64B + 16B pad)
#define TILEB (128 * RS)         // 10240 bytes per tile

__global__ void __launch_bounds__(256, 2)
conv_mma(const float* __restrict__ x, float* __restrict__ out) {
    __shared__ __align__(16) char smem[4 * TILEB];   // AH | AL | BH | BL
    const uint32_t sb = smem_u32(smem);
    const uint32_t AH = 0, AL = TILEB, BH = 2 * TILEB, BL = 3 * TILEB;

    const int tid  = threadIdx.x;
    const int wid  = tid >> 5;
    const int lane = tid & 31;
    const int wm   = wid & 1;          // 2 warps along m
    const int wn   = wid >> 1;         // 4 warps along n

    const int b  = blockIdx.z;
    const int m0 = blockIdx.y * 128;
    const int n0 = blockIdx.x * 128;
    const float* xb = x + (size_t)b * CIN * HW;
    const uint4* kh4 = (const uint4*)g_kh;
    const uint4* kl4 = (const uint4*)g_kl;

    float acc[4][4][4];
    #pragma unroll
    for (int i = 0; i < 4; i++)
        #pragma unroll
        for (int j = 0; j < 4; j++)
            #pragma unroll
            for (int r = 0; r < 4; r++) acc[i][j][r] = 0.f;

    // ldmatrix base addresses for this thread
    const uint32_t lrow = lane & 15;
    const uint32_t lcol = (lane >> 4) * 16;

    for (int stage = 0; stage < 36; stage++) {
        const int k0 = stage * BK;
        // --- A tiles: 128 rows x 32 bf16 (hi & lo), 4x uint4 chunks per row ---
        #pragma unroll
        for (int q = 0; q < 2; q++) {
            int idx = q * 256 + tid;
            int row = idx >> 2;
            int c   = idx & 3;
            size_t e4 = (size_t)(b * COUT + m0 + row) * (KTOT / 8) + (k0 >> 3) + c;
            uint4 vh = kh4[e4];
            uint4 vl = kl4[e4];
            uint32_t dst = (uint32_t)(row * RS + c * 16);
            *(uint4*)(smem + AH + dst) = vh;
            *(uint4*)(smem + AL + dst) = vl;
        }
        // --- B tiles: im2col gather + split, 128 n-rows x 32 k ---
        #pragma unroll
        for (int i = 0; i < 8; i++) {
            int pid = i * 256 + tid;
            int row = pid >> 4;                 // n row in tile
            int pk  = pid & 15;                 // k pair index
            int n = n0 + row;
            int k = k0 + pk * 2;
            float v0 = 0.f, v1 = 0.f;
            if (n < HW) {
                int oh = n / H_, ow = n - oh * H_;
                int ci = k / 9, r = k - ci * 9, kh = r / 3, kw = r - kh * 3;
                int ih = oh + kh - 1, iw = ow + kw - 1;
                if ((unsigned)ih < (unsigned)H_ && (unsigned)iw < (unsigned)H_)
                    v0 = xb[ci * HW + ih * H_ + iw];
                int k1 = k + 1;
                ci = k1 / 9; r = k1 - ci * 9; kh = r / 3; kw = r - kh * 3;
                ih = oh + kh - 1; iw = ow + kw - 1;
                if ((unsigned)ih < (unsigned)H_ && (unsigned)iw < (unsigned)H_)
                    v1 = xb[ci * HW + ih * H_ + iw];
            }
            __nv_bfloat16 h0, l0, h1, l1;
            split_hl(v0, h0, l0);
            split_hl(v1, h1, l1);
            uint32_t dst = (uint32_t)(row * RS + pk * 4);
            *(uint32_t*)(smem + BH + dst) = pack_bf2(h0, h1);
            *(uint32_t*)(smem + BL + dst) = pack_bf2(l0, l1);
        }
        __syncthreads();

        #pragma unroll
        for (int ks = 0; ks < 2; ks++) {
            const uint32_t koff = ks * 32;     // 16 bf16 = 32 bytes
            uint32_t ah[4][4], al[4][4], bb[4][2];
            #pragma unroll
            for (int mi = 0; mi < 4; mi++) {
                uint32_t addr = sb + AH + (wm * 64 + mi * 16 + lrow) * RS + koff + lcol;
                ldmx4(ah[mi], addr);
            }
            #pragma unroll
            for (int mi = 0; mi < 4; mi++) {
                uint32_t addr = sb + AL + (wm * 64 + mi * 16 + lrow) * RS + koff + lcol;
                ldmx4(al[mi], addr);
            }
            // B hi fragments (n32 = 4 n8-frags)
            #pragma unroll
            for (int ni = 0; ni < 2; ni++) {
                uint32_t t[4];
                uint32_t addr = sb + BH + (wn * 32 + ni * 16 + lrow) * RS + koff + lcol;
                ldmx4(t, addr);
                bb[ni * 2 + 0][0] = t[0]; bb[ni * 2 + 0][1] = t[2];
                bb[ni * 2 + 1][0] = t[1]; bb[ni * 2 + 1][1] = t[3];
            }
            #pragma unroll
            for (int mi = 0; mi < 4; mi++)
                #pragma unroll
                for (int nj = 0; nj < 4; nj++) {
                    mma_bf16(acc[mi][nj], ah[mi], bb[nj]);
                    mma_bf16(acc[mi][nj], al[mi], bb[nj]);
                }
            // B lo fragments (overwrite bb)
            #pragma unroll
            for (int ni = 0; ni < 2; ni++) {
                uint32_t t[4];
                uint32_t addr = sb + BL + (wn * 32 + ni * 16 + lrow) * RS + koff + lcol;
                ldmx4(t, addr);
                bb[ni * 2 + 0][0] = t[0]; bb[ni * 2 + 0][1] = t[2];
                bb[ni * 2 + 1][0] = t[1]; bb[ni * 2 + 1][1] = t[3];
            }
            #pragma unroll
            for (int mi = 0; mi < 4; mi++)
                #pragma unroll
                for (int nj = 0; nj < 4; nj++)
                    mma_bf16(acc[mi][nj], ah[mi], bb[nj]);
        }
        __syncthreads();
    }

    // --- epilogue: fragment layout -> gmem (float2 stores) ---
    #pragma unroll
    for (int mi = 0; mi < 4; mi++) {
        const int m = m0 + wm * 64 + mi * 16 + (lane >> 2);
        #pragma unroll
        for (int nj = 0; nj < 4; nj++) {
            const int nn = n0 + wn * 32 + nj * 8 + (lane & 3) * 2;
            if (nn < HW) {
                float* o = out + (size_t)(b * COUT + m) * HW + nn;
                *(float2*)o = make_float2(acc[mi][nj][0], acc[mi][nj][1]);
                *(float2*)(o + 8 * HW) = make_float2(acc[mi][nj][2], acc[mi][nj][3]);
            }
        }
    }
}

// ---------------------------------------------------------------------------
extern "C" void kernel_launch(void* const* d_in, const int* in_sizes, int n_in,
                              void* d_out, int out_size) {
    const float* x     = (const float*)d_in[0];
    const float* convs = (const float*)d_in[1];
    const float* w1    = (const float*)d_in[2];
    const float* b1    = (const float*)d_in[3];
    const float* w2    = (const float*)d_in[4];
    const float* b2    = (const float*)d_in[5];
    float* out = (float*)d_out;

    gap_kernel<<<B_ * CIN, 256>>>(x);
    routing_kernel<<<1, 32>>>(w1, b1, w2, b2);
    mix_kernel<<<dim3(CONV4_PER_E / 256, B_), 256>>>(convs);
    conv_mma<<<dim3((HW + 127) / 128, COUT / 128, B_), 256>>>(x, out);
}

// round 5
// speedup vs baseline: 2.7869x; 1.5966x over previous
#include <cuda_runtime.h>
#include <cuda_bf16.h>
#include <cstdint>

// Problem constants
#define B_    32
#define CIN   128
#define H_    56
#define HW    3136          // 56*56
#define COUT  256
#define KTOT  1152          // CIN*9
#define E_    4
#define R_    16
#define KERN_PER_B (COUT*KTOT)      // 294912

// Scratch (static device arrays; no runtime allocation)
__device__ float g_gap[B_ * CIN];
__device__ float g_routing[B_ * E_];
// Mixed conv kernels, k' = r*128+ci ordering, bf16 hi/lo split: [b][m][k']
__device__ __nv_bfloat16 g_Ah[(size_t)B_ * COUT * KTOT + 64];
__device__ __nv_bfloat16 g_Al[(size_t)B_ * COUT * KTOT + 64];
// 9 shifted zero-padded copies of x, bf16 hi/lo: [r][b][ci][n]
#define XS_ELEMS ((size_t)9 * B_ * CIN * HW)
__device__ __nv_bfloat16 g_Xh[XS_ELEMS + 8192];
__device__ __nv_bfloat16 g_Xl[XS_ELEMS + 8192];

// ---------------------------------------------------------------------------
// helpers
// ---------------------------------------------------------------------------
__device__ __forceinline__ uint32_t smem_u32(const void* p) {
    uint32_t a;
    asm("{ .reg .u64 t; cvta.to.shared.u64 t, %1; cvt.u32.u64 %0, t; }"
        : "=r"(a) : "l"(p));
    return a;
}
__device__ __forceinline__ void ldmx4(uint32_t* r, uint32_t addr) {
    asm volatile("ldmatrix.sync.aligned.m8n8.x4.shared.b16 {%0,%1,%2,%3}, [%4];"
                 : "=r"(r[0]), "=r"(r[1]), "=r"(r[2]), "=r"(r[3]) : "r"(addr));
}
__device__ __forceinline__ void ldmx4t(uint32_t* r, uint32_t addr) {
    asm volatile("ldmatrix.sync.aligned.m8n8.x4.trans.shared.b16 {%0,%1,%2,%3}, [%4];"
                 : "=r"(r[0]), "=r"(r[1]), "=r"(r[2]), "=r"(r[3]) : "r"(addr));
}
__device__ __forceinline__ void mma_bf16(float* d, const uint32_t* a, const uint32_t* b) {
    asm volatile(
        "mma.sync.aligned.m16n8k16.row.col.f32.bf16.bf16.f32 "
        "{%0,%1,%2,%3},{%4,%5,%6,%7},{%8,%9},{%0,%1,%2,%3};"
        : "+f"(d[0]), "+f"(d[1]), "+f"(d[2]), "+f"(d[3])
        : "r"(a[0]), "r"(a[1]), "r"(a[2]), "r"(a[3]), "r"(b[0]), "r"(b[1]));
}
__device__ __forceinline__ void cp16(uint32_t dst, const void* src) {
    asm volatile("cp.async.cg.shared.global [%0], [%1], 16;" :: "r"(dst), "l"(src));
}
__device__ __forceinline__ void cp_commit() {
    asm volatile("cp.async.commit_group;" ::: "memory");
}
__device__ __forceinline__ void split_hl(float v, __nv_bfloat16& h, __nv_bfloat16& l) {
    h = __float2bfloat16_rn(v);
    l = __float2bfloat16_rn(v - __bfloat162float(h));
}
__device__ __forceinline__ uint32_t pack_bf2(__nv_bfloat16 a, __nv_bfloat16 b) {
    __nv_bfloat162 t = __halves2bfloat162(a, b);
    return *reinterpret_cast<uint32_t*>(&t);
}

// ---------------------------------------------------------------------------
// 1) Global average pool
// ---------------------------------------------------------------------------
__global__ void gap_kernel(const float* __restrict__ x) {
    const int idx = blockIdx.x;
    const float* p = x + (size_t)idx * HW;
    float s = 0.f;
    for (int i = threadIdx.x; i < HW; i += 256) s += p[i];
    #pragma unroll
    for (int o = 16; o > 0; o >>= 1) s += __shfl_xor_sync(0xffffffffu, s, o);
    __shared__ float sm[8];
    if ((threadIdx.x & 31) == 0) sm[threadIdx.x >> 5] = s;
    __syncthreads();
    if (threadIdx.x < 8) {
        s = sm[threadIdx.x];
        s += __shfl_xor_sync(0xffu, s, 4);
        s += __shfl_xor_sync(0xffu, s, 2);
        s += __shfl_xor_sync(0xffu, s, 1);
        if (threadIdx.x == 0) g_gap[idx] = s * (1.0f / 3136.0f);
    }
}

// ---------------------------------------------------------------------------
// 2) Router MLP + softmax(logits/30)
// ---------------------------------------------------------------------------
__global__ void routing_kernel(const float* __restrict__ w1, const float* __restrict__ b1,
                               const float* __restrict__ w2, const float* __restrict__ b2) {
    const int b = threadIdx.x;
    if (b >= B_) return;
    float h[R_];
    #pragma unroll
    for (int r = 0; r < R_; r++) {
        float s = b1[r];
        for (int c = 0; c < CIN; c++) s += g_gap[b * CIN + c] * w1[r * CIN + c];
        h[r] = fmaxf(s, 0.f);
    }
    float lg[E_];
    float mx = -1e30f;
    #pragma unroll
    for (int e = 0; e < E_; e++) {
        float s = b2[e];
        #pragma unroll
        for (int r = 0; r < R_; r++) s += h[r] * w2[e * R_ + r];
        lg[e] = s * (1.0f / 30.0f);
        mx = fmaxf(mx, lg[e]);
    }
    float den = 0.f;
    #pragma unroll
    for (int e = 0; e < E_; e++) { lg[e] = __expf(lg[e] - mx); den += lg[e]; }
    const float inv = 1.0f / den;
    #pragma unroll
    for (int e = 0; e < E_; e++) g_routing[b * E_ + e] = lg[e] * inv;
}

// ---------------------------------------------------------------------------
// 3) Shift + pad + bf16-split x into 9 copies: g_X[r][b][ci][n]
//    One block per (b, ci) plane; reads plane once via smem.
// ---------------------------------------------------------------------------
__global__ void shift_kernel(const float* __restrict__ x) {
    __shared__ float plane[HW];
    const int bc = blockIdx.x;               // b*CIN + ci
    const float* src = x + (size_t)bc * HW;
    for (int i = threadIdx.x; i < HW; i += 256) plane[i] = src[i];
    __syncthreads();
    const int b = bc >> 7, ci = bc & 127;
    for (int p = threadIdx.x; p < HW / 2; p += 256) {
        const int n0 = 2 * p;
        const int oh = n0 / H_;
        const int ow = n0 - oh * H_;         // even; ow+1 <= 55 (same row)
        #pragma unroll
        for (int r = 0; r < 9; r++) {
            const int dh = r / 3 - 1, dw = r % 3 - 1;
            const int ih = oh + dh;
            float v0 = 0.f, v1 = 0.f;
            if ((unsigned)ih < (unsigned)H_) {
                const int iw0 = ow + dw;
                if ((unsigned)iw0 < (unsigned)H_) v0 = plane[ih * H_ + iw0];
                const int iw1 = iw0 + 1;
                if ((unsigned)iw1 < (unsigned)H_) v1 = plane[ih * H_ + iw1];
            }
            __nv_bfloat16 h0, l0, h1, l1;
            split_hl(v0, h0, l0);
            split_hl(v1, h1, l1);
            const size_t off = ((size_t)(r * B_ + b) * CIN + ci) * (HW / 2) + p;
            ((uint32_t*)g_Xh)[off] = pack_bf2(h0, h1);
            ((uint32_t*)g_Xl)[off] = pack_bf2(l0, l1);
        }
    }
}

// ---------------------------------------------------------------------------
// 4) Mix expert kernels -> g_A[b][m][k'] with k' = r*128+ci, bf16 hi/lo
// ---------------------------------------------------------------------------
__global__ void mix_kernel(const float* __restrict__ convs) {
    const int m = blockIdx.x;
    const int b = blockIdx.y;
    const float r0 = g_routing[b * 4 + 0];
    const float r1 = g_routing[b * 4 + 1];
    const float r2 = g_routing[b * 4 + 2];
    const float r3 = g_routing[b * 4 + 3];
    for (int p = threadIdx.x; p < KTOT / 2; p += 128) {   // p -> k' pair (2*p, 2*p+1)
        const int r = p >> 6;
        const int ci = (p & 63) * 2;
        const int base = m * KTOT + ci * 9 + r;
        const float* c0 = convs + base;
        float v0 = r0 * c0[0] + r1 * c0[KERN_PER_B] + r2 * c0[2 * KERN_PER_B] + r3 * c0[3 * KERN_PER_B];
        const float* c1 = convs + base + 9;
        float v1 = r0 * c1[0] + r1 * c1[KERN_PER_B] + r2 * c1[2 * KERN_PER_B] + r3 * c1[3 * KERN_PER_B];
        __nv_bfloat16 h0, l0, h1, l1;
        split_hl(v0, h0, l0);
        split_hl(v1, h1, l1);
        const size_t off = (size_t)(b * COUT + m) * (KTOT / 2) + p;
        ((uint32_t*)g_Ah)[off] = pack_bf2(h0, h1);
        ((uint32_t*)g_Al)[off] = pack_bf2(l0, l1);
    }
}

// ---------------------------------------------------------------------------
// 5) Per-sample GEMM on mma.sync, cp.async double-buffered.
//    CTA tile 128m x 128n, BK=32 (36 stages), 8 warps -> warp tile 64m x 32n.
//    smem: A[2][128 rows][128B: hi 4ch | lo 4ch, XOR swizzle]
//          B[2][hi 32 krows x 256B | lo 32 krows x 256B, XOR swizzle]
// ---------------------------------------------------------------------------
#define SM_A(buf)  ((buf) * 16384)
#define SM_B(buf)  (32768 + (buf) * 16384)
#define SM_TOTAL   65536

__global__ void __launch_bounds__(256, 2)
conv_mma(float* __restrict__ out) {
    extern __shared__ __align__(128) char smem[];
    const uint32_t sb = smem_u32(smem);

    const int tid  = threadIdx.x;
    const int wid  = tid >> 5;
    const int lane = tid & 31;
    const int wm   = wid & 1;          // 2 warps along m
    const int wn   = wid >> 1;         // 4 warps along n

    const int b  = blockIdx.z;
    const int m0 = blockIdx.y * 128;
    const int n0 = blockIdx.x * 128;

    float acc[4][4][4];
    #pragma unroll
    for (int i = 0; i < 4; i++)
        #pragma unroll
        for (int j = 0; j < 4; j++)
            #pragma unroll
            for (int q = 0; q < 4; q++) acc[i][j][q] = 0.f;

    // ---- stage loader (all 256 threads, 8 cp.async each) ----
    auto load_stage = [&](int s, int buf) {
        const int r   = s >> 2;
        const int ci0 = (s & 3) * 32;
        // A: 1024 x 16B  (row m 0..127, chunk c 0..7: c<4 hi, else lo)
        #pragma unroll
        for (int q = 0; q < 4; q++) {
            const int id  = q * 256 + tid;
            const int row = id >> 3;
            const int c   = id & 7;
            const __nv_bfloat16* src =
                (c < 4 ? g_Ah : g_Al) + (size_t)(b * COUT + m0 + row) * KTOT + s * 32 + (c & 3) * 8;
            cp16(sb + SM_A(buf) + row * 128 + ((c ^ (row & 7)) * 16), src);
        }
        // B: 1024 x 16B  (krow 0..31, chunk c 0..15, half: hi/lo)
        #pragma unroll
        for (int q = 0; q < 4; q++) {
            const int id   = q * 256 + tid;
            const int half = id >> 9;
            const int kr   = (id >> 4) & 31;
            const int c    = id & 15;
            const __nv_bfloat16* src =
                (half ? g_Xl : g_Xh) + (size_t)((r * B_ + b) * CIN + ci0 + kr) * HW + n0 + c * 8;
            cp16(sb + SM_B(buf) + half * 8192 + kr * 256 + ((c ^ (kr & 7)) * 16), src);
        }
        cp_commit();
    };

    load_stage(0, 0);

    for (int s = 0; s < 36; s++) {
        const int buf = s & 1;
        if (s + 1 < 36) {
            load_stage(s + 1, buf ^ 1);
            asm volatile("cp.async.wait_group 1;" ::: "memory");
        } else {
            asm volatile("cp.async.wait_group 0;" ::: "memory");
        }
        __syncthreads();

        #pragma unroll
        for (int ks = 0; ks < 2; ks++) {
            // ---- A hi fragments ----
            uint32_t ah[4][4];
            #pragma unroll
            for (int mi = 0; mi < 4; mi++) {
                const int row = wm * 64 + mi * 16 + (lane & 15);
                const int cl  = ks * 2 + (lane >> 4);
                ldmx4(ah[mi], sb + SM_A(buf) + row * 128 + ((cl ^ (row & 7)) * 16));
            }
            // ---- B hi + lo fragments (ldmatrix.trans from k-major) ----
            uint32_t bh[4][2], bl[4][2];
            #pragma unroll
            for (int ni = 0; ni < 2; ni++) {
                const int mat = lane >> 3, j = lane & 7;
                const int kr  = ks * 16 + (mat & 1) * 8 + j;
                const int nc  = wn * 4 + ni * 2 + (mat >> 1);
                uint32_t t[4];
                const uint32_t a0 = sb + SM_B(buf) + kr * 256 + ((nc ^ (kr & 7)) * 16);
                ldmx4t(t, a0);
                bh[ni * 2 + 0][0] = t[0]; bh[ni * 2 + 0][1] = t[1];
                bh[ni * 2 + 1][0] = t[2]; bh[ni * 2 + 1][1] = t[3];
                ldmx4t(t, a0 + 8192);
                bl[ni * 2 + 0][0] = t[0]; bl[ni * 2 + 0][1] = t[1];
                bl[ni * 2 + 1][0] = t[2]; bl[ni * 2 + 1][1] = t[3];
            }
            #pragma unroll
            for (int mi = 0; mi < 4; mi++)
                #pragma unroll
                for (int nj = 0; nj < 4; nj++) {
                    mma_bf16(acc[mi][nj], ah[mi], bh[nj]);
                    mma_bf16(acc[mi][nj], ah[mi], bl[nj]);
                }
            // ---- A lo fragments ----
            uint32_t al[4][4];
            #pragma unroll
            for (int mi = 0; mi < 4; mi++) {
                const int row = wm * 64 + mi * 16 + (lane & 15);
                const int cl  = 4 + ks * 2 + (lane >> 4);
                ldmx4(al[mi], sb + SM_A(buf) + row * 128 + ((cl ^ (row & 7)) * 16));
            }
            #pragma unroll
            for (int mi = 0; mi < 4; mi++)
                #pragma unroll
                for (int nj = 0; nj < 4; nj++)
                    mma_bf16(acc[mi][nj], al[mi], bh[nj]);
        }
        __syncthreads();
    }

    // ---- epilogue ----
    #pragma unroll
    for (int mi = 0; mi < 4; mi++) {
        const int m = m0 + wm * 64 + mi * 16 + (lane >> 2);
        #pragma unroll
        for (int nj = 0; nj < 4; nj++) {
            const int nn = n0 + wn * 32 + nj * 8 + (lane & 3) * 2;
            if (nn < HW) {
                float* o = out + (size_t)(b * COUT + m) * HW + nn;
                *(float2*)o = make_float2(acc[mi][nj][0], acc[mi][nj][1]);
                *(float2*)(o + 8 * HW) = make_float2(acc[mi][nj][2], acc[mi][nj][3]);
            }
        }
    }
}

// ---------------------------------------------------------------------------
extern "C" void kernel_launch(void* const* d_in, const int* in_sizes, int n_in,
                              void* d_out, int out_size) {
    const float* x     = (const float*)d_in[0];
    const float* convs = (const float*)d_in[1];
    const float* w1    = (const float*)d_in[2];
    const float* b1    = (const float*)d_in[3];
    const float* w2    = (const float*)d_in[4];
    const float* b2    = (const float*)d_in[5];
    float* out = (float*)d_out;

    cudaFuncSetAttribute(conv_mma, cudaFuncAttributeMaxDynamicSharedMemorySize, SM_TOTAL);

    gap_kernel<<<B_ * CIN, 256>>>(x);
    routing_kernel<<<1, 32>>>(w1, b1, w2, b2);
    shift_kernel<<<B_ * CIN, 256>>>(x);
    mix_kernel<<<dim3(COUT, B_), 128>>>(convs);
    conv_mma<<<dim3((HW + 127) / 128, COUT / 128, B_), 256, SM_TOTAL>>>(out);
}